// round 1
// baseline (speedup 1.0000x reference)
#include <cuda_runtime.h>

// Problem constants (hard-coded by the reference)
#define B_  128
#define C1_ 128
#define C2_ 14
#define S_  14
#define K_  3
#define H_  256
#define E_  2

// Scratch for the intermediate t4 tensor, stored directly in the OUTPUT
// layout [b][h][n][m] so the epilogue is a coalesced gather.
// 128*256*14*14 floats = 25.7 MB.
__device__ float g_t4[(size_t)B_ * H_ * C2_ * S_];

// ---------------------------------------------------------------------------
// Kernel 1: t4[b,n,m,h] = sum_{j<128, i<3} xpad[b,j,n,m+i] * w1[j,i,h]
// Block = (n, b). 256 threads, thread tid owns h = tid.
// x slice for (b,n) lives in smem as xs[j][0..15] (zero-padded conv window).
// ---------------------------------------------------------------------------
__global__ __launch_bounds__(256) void conv_t4_kernel(
    const float* __restrict__ x,   // (B, C1*C2, S)
    const float* __restrict__ w1)  // (C1, K, H)
{
    const int n = blockIdx.x;      // 0..13
    const int b = blockIdx.y;      // 0..127

    __shared__ float xs[C1_][16];

    const int tid = threadIdx.x;

    // x[b, j*C2 + n, m]  ->  base + j*(C2*S) + m
    const float* xb = x + (size_t)b * (C1_ * C2_ * S_) + n * S_;
    for (int idx = tid; idx < C1_ * S_; idx += 256) {
        int j = idx / S_;
        int m = idx - j * S_;
        xs[j][m + 1] = xb[j * (C2_ * S_) + m];
    }
    if (tid < C1_) { xs[tid][0] = 0.0f; xs[tid][15] = 0.0f; }
    __syncthreads();

    const int h = tid;
    float acc[S_];
#pragma unroll
    for (int m = 0; m < S_; ++m) acc[m] = 0.0f;

    const float* wp = w1 + h;      // w1[j,i,h] at (j*K + i)*H + h

    for (int j = 0; j < C1_; ++j) {
        float xr[16];
#pragma unroll
        for (int p = 0; p < 16; ++p) xr[p] = xs[j][p];
#pragma unroll
        for (int i = 0; i < K_; ++i) {
            float wv = __ldg(wp + (j * K_ + i) * H_);
#pragma unroll
            for (int m = 0; m < S_; ++m)
                acc[m] = fmaf(xr[m + i], wv, acc[m]);
        }
    }

    // Store to scratch in output layout [b][h][n][m] (14 floats, 8B-aligned)
    float* o = g_t4 + (((size_t)b * H_ + h) * C2_ + n) * S_;
#pragma unroll
    for (int mm = 0; mm < 7; ++mm)
        reinterpret_cast<float2*>(o)[mm] = make_float2(acc[2 * mm], acc[2 * mm + 1]);
}

// ---------------------------------------------------------------------------
// Kernel 2: epilogue. Implements both rolls + outer-product-with-w0 + sum(E).
//   out[b,h,n,m] = sum_e t4[b, (n1_e - s)%14, m, h_layout...] * w0[h, e1_e]
// where (n1_e, e1_e) come from unflattening g = (n*2 + e - s) mod 28.
// For s=1 this is t4[(n-2)%14]*w0[h,1] + t4[(n-1)%14]*w0[h,0].
// ---------------------------------------------------------------------------
__global__ __launch_bounds__(256) void epilogue_kernel(
    const float* __restrict__ w0,       // (H, E)
    const int*   __restrict__ shift_p,  // may be null -> shift = 1
    float*       __restrict__ out)      // (B, H, C2, S)
{
    const int total = B_ * H_ * C2_ * S_;
    int idx = blockIdx.x * blockDim.x + threadIdx.x;
    if (idx >= total) return;

    const int m = idx % S_;
    const int n = (idx / S_) % C2_;
    const int h = (idx / (S_ * C2_)) % H_;
    const int b = idx / (S_ * C2_ * H_);

    const int s   = shift_p ? shift_p[0] : 1;
    const int s28 = ((s % 28) + 28) % 28;
    const int s14 = ((s % 14) + 14) % 14;

    const float* plane = g_t4 + ((size_t)b * H_ + h) * (C2_ * S_);

    float val = 0.0f;
#pragma unroll
    for (int e = 0; e < E_; ++e) {
        int g  = (n * E_ + e - s28 + 28) % 28;  // merged-axis roll (size 28)
        int n1 = g >> 1;
        int e1 = g & 1;
        int n2 = (n1 - s14 + 14) % 14;          // C2-axis roll (size 14)
        val += plane[n2 * S_ + m] * __ldg(w0 + h * E_ + e1);
    }
    out[idx] = val;
}

// ---------------------------------------------------------------------------
extern "C" void kernel_launch(void* const* d_in, const int* in_sizes, int n_in,
                              void* d_out, int out_size)
{
    const float* x     = (const float*)d_in[0];
    const float* w0    = (const float*)d_in[1];
    const float* w1    = (const float*)d_in[2];
    const int*   shift = (n_in >= 4) ? (const int*)d_in[3] : nullptr;

    (void)in_sizes; (void)out_size;

    dim3 grid1(C2_, B_);
    conv_t4_kernel<<<grid1, 256>>>(x, w1);

    const int total = B_ * H_ * C2_ * S_;
    epilogue_kernel<<<(total + 255) / 256, 256>>>(w0, shift, (float*)d_out);
}

// round 2
// speedup vs baseline: 1.1152x; 1.1152x over previous
#include <cuda_runtime.h>

// Problem constants (hard-coded by the reference)
#define B_  128
#define C1_ 128
#define C2_ 14
#define S_  14
#define K_  3
#define H_  256
#define E_  2

typedef unsigned long long u64;

// Scratch for the intermediate t4 tensor, stored in the OUTPUT layout
// [b][h][n][m] so the epilogue is a coalesced gather. 25.7 MB.
__device__ float g_t4[(size_t)B_ * H_ * C2_ * S_];

// Packed dual-fp32 FMA: d.lo = a.lo*b.lo + c.lo ; d.hi = a.hi*b.hi + c.hi
__device__ __forceinline__ u64 ffma2(u64 a, u64 b, u64 c) {
    u64 d;
    asm("fma.rn.f32x2 %0, %1, %2, %3;" : "=l"(d) : "l"(a), "l"(b), "l"(c));
    return d;
}

__device__ __forceinline__ u64 dupf(float v) {
    unsigned u = __float_as_uint(v);
    return (u64)u | ((u64)u << 32);
}

// ---------------------------------------------------------------------------
// Kernel 1: t4[b,n,m,h] = sum_{j<128, i<3} xpad[b,j,n,m+i] * w1[j,i,h]
// Block = (n-pair, b). 256 threads: tid/128 selects n within the pair,
// hp = tid%128 selects an h-PAIR (h0=2hp, h1=2hp+1). Each thread computes
// 14 packed accumulators (t4[...,h0], t4[...,h1]) via fma.rn.f32x2.
// x window lives in smem pre-DUPLICATED as (x,x) pairs -> operand packs free.
// ---------------------------------------------------------------------------
__global__ __launch_bounds__(256) void conv_t4_kernel(
    const float* __restrict__ x,   // (B, C1*C2, S)
    const float* __restrict__ w1)  // (C1, K, H)
{
    const int n0 = blockIdx.x * 2;  // first n of the pair
    const int b  = blockIdx.y;

    __shared__ u64 xs[2][C1_][16];  // (x,x) duplicated, zero-padded window

    const int tid = threadIdx.x;

    // Zero the two pad columns (p=0 and p=15)
    for (int idx = tid; idx < 2 * C1_ * 2; idx += 256) {
        int nn = idx >> 8;            // /(128*2)
        int r  = idx & 255;
        int j  = r >> 1;
        int p  = (r & 1) ? 15 : 0;
        xs[nn][j][p] = 0ull;
    }
    // Fill interior: xs[nn][j][m+1] = dup(x[b, j*C2 + (n0+nn), m])
    const float* xb = x + (size_t)b * (C1_ * C2_ * S_);
    for (int idx = tid; idx < 2 * C1_ * S_; idx += 256) {
        int nn = idx / (C1_ * S_);
        int r  = idx - nn * (C1_ * S_);
        int j  = r / S_;
        int m  = r - j * S_;
        float v = xb[(j * C2_ + n0 + nn) * S_ + m];
        xs[nn][j][m + 1] = dupf(v);
    }
    __syncthreads();

    const int nn = tid >> 7;        // 0 or 1
    const int hp = tid & 127;       // h-pair index; h0 = 2*hp

    u64 acc[S_];
#pragma unroll
    for (int m = 0; m < S_; ++m) acc[m] = 0ull;

    // w1[j,i,h] at (j*K+i)*H + h ; pair (h0,h1) is an aligned float2
    const u64* wp = reinterpret_cast<const u64*>(w1) + hp;

#pragma unroll 2
    for (int j = 0; j < C1_; ++j) {
        u64 xd[16];
#pragma unroll
        for (int p = 0; p < 16; ++p) xd[p] = xs[nn][j][p];
        u64 w[K_];
#pragma unroll
        for (int i = 0; i < K_; ++i) w[i] = __ldg(wp + (size_t)(j * K_ + i) * (H_ / 2));
#pragma unroll
        for (int i = 0; i < K_; ++i) {
#pragma unroll
            for (int m = 0; m < S_; ++m)
                acc[m] = ffma2(xd[m + i], w[i], acc[m]);
        }
    }

    // Unpack and store two rows: [b][h0][n][m] and [b][h1][n][m]
    const int n = n0 + nn;
    float lo[S_], hi[S_];
#pragma unroll
    for (int m = 0; m < S_; ++m) {
        lo[m] = __uint_as_float((unsigned)(acc[m]));
        hi[m] = __uint_as_float((unsigned)(acc[m] >> 32));
    }
    float* o0 = g_t4 + (((size_t)b * H_ + 2 * hp)     * C2_ + n) * S_;
    float* o1 = g_t4 + (((size_t)b * H_ + 2 * hp + 1) * C2_ + n) * S_;
#pragma unroll
    for (int mm = 0; mm < 7; ++mm) {
        reinterpret_cast<float2*>(o0)[mm] = make_float2(lo[2 * mm], lo[2 * mm + 1]);
        reinterpret_cast<float2*>(o1)[mm] = make_float2(hi[2 * mm], hi[2 * mm + 1]);
    }
}

// ---------------------------------------------------------------------------
// Kernel 2: epilogue, one thread per (b,h,n) OUTPUT ROW (14 elements).
// All modular index math hoisted out of the m loop; body is pure f32x2
// multiply-add on two source rows.
//   out[b,h,n,m] = t4[b,h,n2a,m]*w0[h,e1a] + t4[b,h,n2b,m]*w0[h,e1b]
// ---------------------------------------------------------------------------
__global__ __launch_bounds__(256) void epilogue_kernel(
    const float* __restrict__ w0,       // (H, E)
    const int*   __restrict__ shift_p,  // may be null -> shift = 1
    float*       __restrict__ out)      // (B, H, C2, S)
{
    const int total = B_ * H_ * C2_;
    int idx = blockIdx.x * blockDim.x + threadIdx.x;
    if (idx >= total) return;

    const int n = idx % C2_;
    const int h = (idx / C2_) % H_;

    const int s   = shift_p ? shift_p[0] : 1;
    const int s28 = ((s % 28) + 28) % 28;
    const int s14 = ((s % 14) + 14) % 14;

    int n2[E_];
    float wv[E_];
    const float2 w0p = __ldg(reinterpret_cast<const float2*>(w0) + h);
#pragma unroll
    for (int e = 0; e < E_; ++e) {
        int g  = (n * E_ + e - s28 + 56) % 28;  // merged-axis roll (size 28)
        int n1 = g >> 1;
        int e1 = g & 1;
        n2[e] = (n1 - s14 + 14) % 14;           // C2-axis roll (size 14)
        wv[e] = e1 ? w0p.y : w0p.x;
    }

    const float* plane = g_t4 + (size_t)(idx / C2_) * (C2_ * S_);
    const float2* pa = reinterpret_cast<const float2*>(plane + n2[0] * S_);
    const float2* pb = reinterpret_cast<const float2*>(plane + n2[1] * S_);
    float2* o = reinterpret_cast<float2*>(out + (size_t)idx * S_);

#pragma unroll
    for (int mm = 0; mm < 7; ++mm) {
        float2 va = __ldg(pa + mm);
        float2 vb = __ldg(pb + mm);
        float2 r;
        r.x = va.x * wv[0] + vb.x * wv[1];
        r.y = va.y * wv[0] + vb.y * wv[1];
        o[mm] = r;
    }
}

// ---------------------------------------------------------------------------
extern "C" void kernel_launch(void* const* d_in, const int* in_sizes, int n_in,
                              void* d_out, int out_size)
{
    const float* x     = (const float*)d_in[0];
    const float* w0    = (const float*)d_in[1];
    const float* w1    = (const float*)d_in[2];
    const int*   shift = (n_in >= 4) ? (const int*)d_in[3] : nullptr;

    (void)in_sizes; (void)out_size;

    dim3 grid1(C2_ / 2, B_);
    conv_t4_kernel<<<grid1, 256>>>(x, w1);

    const int total = B_ * H_ * C2_;
    epilogue_kernel<<<(total + 255) / 256, 256>>>(w0, shift, (float*)d_out);
}